// round 1
// baseline (speedup 1.0000x reference)
#include <cuda_runtime.h>
#include <math.h>

#define BB 512
#define SS 128
#define EE 300
#define LL 2
#define HH 300
#define FCIN 1800   // E*(1+L)*2

// ---------------- device scratch (no allocation allowed) ----------------
__device__ float g_s1[BB*SS*EE];
__device__ float g_s2[BB*SS*EE];
__device__ float g_f1[BB*SS*EE];
__device__ float g_f2[BB*SS*EE];
__device__ float g_o1[BB*SS*EE];
__device__ float g_o2[BB*SS*EE];
__device__ float g_A [BB*SS*SS];
__device__ float g_w1[BB*SS];
__device__ float g_w2[BB*SS];
__device__ float g_x [BB*FCIN];
__device__ float g_h [BB*HH];

// ---------------- embedding gather ----------------
__global__ void k_gather(const int* __restrict__ seq1, const int* __restrict__ seq2,
                         const float* __restrict__ emb) {
    int b = blockIdx.x, s = blockIdx.y;
    int base = (b*SS + s)*EE;
    int t1 = seq1[b*SS + s];
    int t2 = seq2[b*SS + s];
    const float* e1 = emb + (long)t1*EE;
    const float* e2 = emb + (long)t2*EE;
    for (int e = threadIdx.x; e < EE; e += blockDim.x) {
        g_s1[base+e] = e1[e];
        g_s2[base+e] = e2[e];
    }
}

// ---------------- mean over S, writes into feature vector g_x ----------------
// sel=0: s1/s2 ; sel=1: o1/o2.  slot: 0..2 (res1 slot; res2 goes to slot+3)
__global__ void k_mean(int sel, int slot) {
    int b = blockIdx.x;
    int e = blockIdx.y*128 + threadIdx.x;
    if (e >= EE) return;
    const float* X = (sel ? g_o1 : g_s1) + b*SS*EE;
    const float* Y = (sel ? g_o2 : g_s2) + b*SS*EE;
    float a1 = 0.f, a2 = 0.f;
    for (int s = 0; s < SS; s++) { a1 += X[s*EE+e]; a2 += Y[s*EE+e]; }
    g_x[b*FCIN + slot*EE + e]     = a1*(1.f/SS);
    g_x[b*FCIN + (3+slot)*EE + e] = a2*(1.f/SS);
}

// ---------------- clear w1/w2 ----------------
__global__ void k_clearw() {
    int b = blockIdx.x, t = threadIdx.x;  // 128 threads
    g_w1[b*SS + t] = 0.f;
    g_w2[b*SS + t] = 0.f;
}

// ---------------- match-score: one CTA per batch, 128x128 output ----------------
// mode=0: inputs s1/s2, store A to g_A
// mode=1: inputs o1/o2, no store; accumulate row sums->g_w1, col sums->g_w2
#define KT 8
__global__ __launch_bounds__(256) void k_match(const int* __restrict__ seq1,
                                               const int* __restrict__ seq2, int mode) {
    int b = blockIdx.x;
    const float* X = (mode ? g_o1 : g_s1) + b*SS*EE;
    const float* Y = (mode ? g_o2 : g_s2) + b*SS*EE;
    __shared__ float v1[SS], v2[SS], n1[SS], n2[SS];
    __shared__ float As[KT][SS+4];
    __shared__ float Bs[KT][SS+4];
    int tid = threadIdx.x;
    if (tid < SS) v1[tid] = (seq1[b*SS + tid] != 0) ? 1.f : 0.f;
    else          v2[tid-SS] = (seq2[b*SS + (tid-SS)] != 0) ? 1.f : 0.f;
    __syncthreads();

    int ty = tid >> 4, tx = tid & 15;         // 16x16 thread grid, 8x8 micro-tile
    int rown = tid & 127, which = tid >> 7;   // norm computation assignment

    float acc[8][8];
#pragma unroll
    for (int u = 0; u < 8; u++)
#pragma unroll
        for (int v = 0; v < 8; v++) acc[u][v] = 0.f;
    float nacc = 0.f;

    for (int k0 = 0; k0 < EE; k0 += KT) {
        __syncthreads();
#pragma unroll 4
        for (int i = tid; i < KT*SS; i += 256) {
            int r = i >> 3, kk = i & 7;
            int k = k0 + kk;
            float xv = 0.f, yv = 0.f;
            if (k < EE) { xv = X[r*EE + k] * v1[r]; yv = Y[r*EE + k] * v2[r]; }
            As[kk][r] = xv;
            Bs[kk][r] = yv;
        }
        __syncthreads();
#pragma unroll
        for (int kk = 0; kk < KT; kk++) {
            float nv = which ? Bs[kk][rown] : As[kk][rown];
            nacc += nv*nv;
            float4 a0 = *(const float4*)&As[kk][ty*8];
            float4 a1 = *(const float4*)&As[kk][ty*8 + 4];
            float4 b0 = *(const float4*)&Bs[kk][tx*8];
            float4 b1 = *(const float4*)&Bs[kk][tx*8 + 4];
            float a[8]  = {a0.x,a0.y,a0.z,a0.w,a1.x,a1.y,a1.z,a1.w};
            float bb[8] = {b0.x,b0.y,b0.z,b0.w,b1.x,b1.y,b1.z,b1.w};
#pragma unroll
            for (int u = 0; u < 8; u++)
#pragma unroll
                for (int v = 0; v < 8; v++) acc[u][v] += a[u]*bb[v];
        }
    }
    __syncthreads();
    if (which) n2[rown] = nacc; else n1[rown] = nacc;
    __syncthreads();

    if (mode == 0) {
#pragma unroll
        for (int u = 0; u < 8; u++) {
            int r = ty*8 + u;
#pragma unroll
            for (int v = 0; v < 8; v++) {
                int c = tx*8 + v;
                float d2 = n1[r] + n2[c] - 2.f*acc[u][v];
                float d = sqrtf(fmaxf(d2, 0.f));
                g_A[(b*SS + r)*SS + c] = 1.f/(1.f + d);
            }
        }
    } else {
        float colsum[8];
#pragma unroll
        for (int v = 0; v < 8; v++) colsum[v] = 0.f;
#pragma unroll
        for (int u = 0; u < 8; u++) {
            int r = ty*8 + u;
            float rowsum = 0.f;
#pragma unroll
            for (int v = 0; v < 8; v++) {
                int c = tx*8 + v;
                float d2 = n1[r] + n2[c] - 2.f*acc[u][v];
                float d = sqrtf(fmaxf(d2, 0.f));
                float a = 1.f/(1.f + d);
                rowsum += a;
                colsum[v] += a;
            }
            atomicAdd(&g_w1[b*SS + r], rowsum);
        }
#pragma unroll
        for (int v = 0; v < 8; v++) atomicAdd(&g_w2[b*SS + tx*8 + v], colsum[v]);
    }
}

// ---------------- f1 = A @ W[l], f2 = A^T @ W[l] ----------------
// grid (B, ceil(E/64)=5, 2), block 256 (16x16), micro 8x4, K=128
__global__ __launch_bounds__(256) void k_fgemm(const float* __restrict__ W, int layer) {
    int b = blockIdx.x;
    int n0 = blockIdx.y * 64;
    int tflag = blockIdx.z;     // 0 -> f1 (A), 1 -> f2 (A^T)
    const float* Ab = g_A + b*SS*SS;
    const float* Wl = W + layer*SS*EE;
    float* out = (tflag ? g_f2 : g_f1) + b*SS*EE;
    __shared__ float As[8][SS+4];
    __shared__ float Ws[8][68];
    int tid = threadIdx.x, ty = tid >> 4, tx = tid & 15;

    float acc[8][4];
#pragma unroll
    for (int u = 0; u < 8; u++)
#pragma unroll
        for (int v = 0; v < 4; v++) acc[u][v] = 0.f;

    for (int k0 = 0; k0 < SS; k0 += 8) {
        __syncthreads();
        if (tflag == 0) {
#pragma unroll 4
            for (int i = tid; i < 8*SS; i += 256) {
                int r = i >> 3, kk = i & 7;
                As[kk][r] = Ab[r*SS + k0 + kk];
            }
        } else {
#pragma unroll 4
            for (int i = tid; i < 8*SS; i += 256) {
                int r = i & 127, kk = i >> 7;
                As[kk][r] = Ab[(k0 + kk)*SS + r];
            }
        }
#pragma unroll 2
        for (int i = tid; i < 8*64; i += 256) {
            int c = i & 63, kk = i >> 6;
            int n = n0 + c;
            Ws[kk][c] = (n < EE) ? Wl[(k0 + kk)*EE + n] : 0.f;
        }
        __syncthreads();
#pragma unroll
        for (int kk = 0; kk < 8; kk++) {
            float4 a0 = *(const float4*)&As[kk][ty*8];
            float4 a1 = *(const float4*)&As[kk][ty*8 + 4];
            float4 w4 = *(const float4*)&Ws[kk][tx*4];
            float a[8] = {a0.x,a0.y,a0.z,a0.w,a1.x,a1.y,a1.z,a1.w};
            float w[4] = {w4.x,w4.y,w4.z,w4.w};
#pragma unroll
            for (int u = 0; u < 8; u++)
#pragma unroll
                for (int v = 0; v < 4; v++) acc[u][v] += a[u]*w[v];
        }
    }
#pragma unroll
    for (int u = 0; u < 8; u++) {
        int r = ty*8 + u;
#pragma unroll
        for (int v = 0; v < 4; v++) {
            int c = n0 + tx*4 + v;
            if (c < EE) out[r*EE + c] = acc[u][v];
        }
    }
}

// ---------------- conv 2in->1out 3x3 + tanh ----------------
// grid (B, S, 2), block 128
__global__ void k_conv(const float* __restrict__ cw, const float* __restrict__ cb, int layer) {
    int b = blockIdx.x, s = blockIdx.y, pair = blockIdx.z;
    const float* X0 = (pair ? g_s2 : g_s1) + b*SS*EE;
    const float* X1 = (pair ? g_f2 : g_f1) + b*SS*EE;
    float* O = (pair ? g_o2 : g_o1) + b*SS*EE;
    __shared__ float xs[2][3][EE+2];
    __shared__ float w[18];
    int tid = threadIdx.x;
    if (tid < 18) w[tid] = cw[layer*18 + tid];
    if (tid < 12) {                 // zero the side padding
        int c = tid / 6, rem = tid % 6;
        int j = rem >> 1, side = rem & 1;
        xs[c][j][side ? EE+1 : 0] = 0.f;
    }
#pragma unroll
    for (int c = 0; c < 2; c++) {
        const float* X = c ? X1 : X0;
#pragma unroll
        for (int j = 0; j < 3; j++) {
            int r = s + j - 1;
            bool ok = (r >= 0 && r < SS);
            for (int e = tid; e < EE; e += 128)
                xs[c][j][e+1] = ok ? X[r*EE + e] : 0.f;
        }
    }
    float bias = cb[layer];
    __syncthreads();
    for (int e = tid; e < EE; e += 128) {
        float acc = bias;
#pragma unroll
        for (int c = 0; c < 2; c++)
#pragma unroll
            for (int kh = 0; kh < 3; kh++)
#pragma unroll
                for (int kw = 0; kw < 3; kw++)
                    acc += w[c*9 + kh*3 + kw] * xs[c][kh][e + kw];
        O[s*EE + e] = tanhf(acc);
    }
}

// ---------------- weighted avg-pool3 + residual update of s ----------------
// grid (B, S, 2), block 128
__global__ void k_pool() {
    int b = blockIdx.x, s = blockIdx.y, pair = blockIdx.z;
    const float* O = (pair ? g_o2 : g_o1) + b*SS*EE;
    float* Sx = (pair ? g_s2 : g_s1) + b*SS*EE;
    const float* wv = (pair ? g_w2 : g_w1) + b*SS;
    float wm = (s > 0)    ? wv[s-1] : 0.f;
    float w0 = wv[s];
    float wp = (s < SS-1) ? wv[s+1] : 0.f;
    for (int e = threadIdx.x; e < EE; e += 128) {
        float t = O[s*EE + e] * w0;
        if (s > 0)    t += O[(s-1)*EE + e] * wm;
        if (s < SS-1) t += O[(s+1)*EE + e] * wp;
        Sx[s*EE + e] += t * (1.f/3.f);
    }
}

// ---------------- fc1 GEMM: [512,1800] @ [1800,300] -> g_h ----------------
// grid (8, 5), block 256 (16x16), micro 4x4
__global__ __launch_bounds__(256) void k_fc1(const float* __restrict__ fw) {
    int m0 = blockIdx.x * 64, n0 = blockIdx.y * 64;
    __shared__ float Xs[8][68];
    __shared__ float Ws[8][68];
    int tid = threadIdx.x, ty = tid >> 4, tx = tid & 15;
    float acc[4][4];
#pragma unroll
    for (int u = 0; u < 4; u++)
#pragma unroll
        for (int v = 0; v < 4; v++) acc[u][v] = 0.f;

    for (int k0 = 0; k0 < FCIN; k0 += 8) {
        __syncthreads();
#pragma unroll 2
        for (int i = tid; i < 512; i += 256) {
            int r = i >> 3, kk = i & 7;
            Xs[kk][r] = g_x[(m0 + r)*FCIN + k0 + kk];
            int n = n0 + r;
            Ws[kk][r] = (n < HH) ? fw[n*FCIN + k0 + kk] : 0.f;
        }
        __syncthreads();
#pragma unroll
        for (int kk = 0; kk < 8; kk++) {
            float4 xa = *(const float4*)&Xs[kk][ty*4];
            float4 wb = *(const float4*)&Ws[kk][tx*4];
            float xv[4] = {xa.x, xa.y, xa.z, xa.w};
            float wv[4] = {wb.x, wb.y, wb.z, wb.w};
#pragma unroll
            for (int u = 0; u < 4; u++)
#pragma unroll
                for (int v = 0; v < 4; v++) acc[u][v] += xv[u]*wv[v];
        }
    }
#pragma unroll
    for (int u = 0; u < 4; u++) {
        int m = m0 + ty*4 + u;
#pragma unroll
        for (int v = 0; v < 4; v++) {
            int n = n0 + tx*4 + v;
            if (n < HH) g_h[m*HH + n] = acc[u][v];
        }
    }
}

// ---------------- LN + relu + fc2 + softmax ----------------
__device__ __forceinline__ float block_reduce512(float v, float* red) {
    int tid = threadIdx.x;
    red[tid] = v;
    __syncthreads();
    for (int off = 256; off > 0; off >>= 1) {
        if (tid < off) red[tid] += red[tid + off];
        __syncthreads();
    }
    float r = red[0];
    __syncthreads();
    return r;
}

__global__ __launch_bounds__(512) void k_head(const float* __restrict__ fc1b,
                                              const float* __restrict__ lng,
                                              const float* __restrict__ lnb,
                                              const float* __restrict__ fc2w,
                                              const float* __restrict__ fc2b,
                                              float* __restrict__ out) {
    int b = blockIdx.x, tid = threadIdx.x;
    __shared__ float red[512];
    bool act = tid < HH;
    float h = act ? (g_h[b*HH + tid] + fc1b[tid]) : 0.f;
    float mu = block_reduce512(h, red) * (1.f/HH);
    float d = act ? (h - mu) : 0.f;
    float var = block_reduce512(d*d, red) * (1.f/HH);
    float hn = 0.f;
    if (act) {
        hn = d * rsqrtf(var + 1e-5f) * lng[tid] + lnb[tid];
        hn = fmaxf(hn, 0.f);
    }
    float o0 = block_reduce512(act ? hn*fc2w[tid]      : 0.f, red);
    float o1 = block_reduce512(act ? hn*fc2w[HH + tid] : 0.f, red);
    if (tid == 0) {
        o0 += fc2b[0];
        o1 += fc2b[1];
        out[b*2 + 0] = o0;
        out[b*2 + 1] = o1;
        float m = fmaxf(o0, o1);
        float e0 = expf(o0 - m), e1 = expf(o1 - m);
        float inv = 1.f/(e0 + e1);
        out[BB*2 + b*2 + 0] = e0*inv;
        out[BB*2 + b*2 + 1] = e1*inv;
    }
}

// ---------------- launch ----------------
extern "C" void kernel_launch(void* const* d_in, const int* in_sizes, int n_in,
                              void* d_out, int out_size) {
    (void)in_sizes; (void)n_in; (void)out_size;
    const int*   seq1 = (const int*)d_in[0];
    const int*   seq2 = (const int*)d_in[1];
    const float* emb  = (const float*)d_in[2];
    const float* W    = (const float*)d_in[3];
    const float* cw   = (const float*)d_in[4];
    const float* cb   = (const float*)d_in[5];
    const float* fc1w = (const float*)d_in[6];
    const float* fc1b = (const float*)d_in[7];
    const float* lng  = (const float*)d_in[8];
    const float* lnb  = (const float*)d_in[9];
    const float* fc2w = (const float*)d_in[10];
    const float* fc2b = (const float*)d_in[11];
    float* out = (float*)d_out;

    k_gather<<<dim3(BB, SS), 128>>>(seq1, seq2, emb);
    k_mean<<<dim3(BB, 3), 128>>>(0, 0);
    for (int l = 0; l < LL; l++) {
        k_match<<<BB, 256>>>(seq1, seq2, 0);
        k_fgemm<<<dim3(BB, 5, 2), 256>>>(W, l);
        k_conv<<<dim3(BB, SS, 2), 128>>>(cw, cb, l);
        k_mean<<<dim3(BB, 3), 128>>>(1, 1 + l);
        k_clearw<<<BB, 128>>>();
        k_match<<<BB, 256>>>(seq1, seq2, 1);
        k_pool<<<dim3(BB, SS, 2), 128>>>();
    }
    k_fc1<<<dim3(8, 5), 256>>>(fc1w);
    k_head<<<BB, 512>>>(fc1b, lng, lnb, fc2w, fc2b, out);
}

// round 2
// speedup vs baseline: 1.3491x; 1.3491x over previous
#include <cuda_runtime.h>
#include <math.h>

#define BB 512
#define SS 128
#define EE 300
#define LL 2
#define HH 300
#define FCIN 1800   // E*(1+L)*2
#define KT 8
#define NCH 38      // ceil(300/8)
#define CROWS 16

// ---------------- device scratch (no allocation allowed) ----------------
__device__ float g_s1[BB*SS*EE];
__device__ float g_s2[BB*SS*EE];
__device__ float g_f1[BB*SS*EE];
__device__ float g_f2[BB*SS*EE];
__device__ float g_o1[BB*SS*EE];
__device__ float g_o2[BB*SS*EE];
__device__ float g_A [BB*SS*SS];
__device__ float g_w1[BB*SS];
__device__ float g_w2[BB*SS];
__device__ float g_v1[BB*SS];
__device__ float g_v2[BB*SS];
__device__ float g_x [BB*FCIN];
__device__ float g_h [BB*HH];

__device__ __forceinline__ float tanh_fast(float x) {
    float r; asm("tanh.approx.f32 %0, %1;" : "=f"(r) : "f"(x)); return r;
}

// ---------------- embedding gather (+ valid masks), float4 ----------------
__global__ __launch_bounds__(256) void k_gather(const int* __restrict__ seq1,
                                                const int* __restrict__ seq2,
                                                const float* __restrict__ emb) {
    int b = blockIdx.x;
    int warp = threadIdx.x >> 5, lane = threadIdx.x & 31;
    for (int i = threadIdx.x; i < SS; i += 256) {
        g_v1[b*SS+i] = (seq1[b*SS+i] != 0) ? 1.f : 0.f;
        g_v2[b*SS+i] = (seq2[b*SS+i] != 0) ? 1.f : 0.f;
    }
    for (int idx = warp; idx < 2*SS; idx += 8) {
        int s = idx >> 1, sel = idx & 1;
        int tok = sel ? seq2[b*SS+s] : seq1[b*SS+s];
        const float4* src = (const float4*)(emb + (long)tok*EE);
        float4* dst = (float4*)((sel ? g_s2 : g_s1) + (b*SS+s)*EE);
        for (int j = lane; j < EE/4; j += 32) dst[j] = src[j];
    }
}

// ---------------- mean over S -> g_x slots ----------------
__global__ void k_mean(int sel, int slot) {
    int b = blockIdx.x;
    int e = blockIdx.y*128 + threadIdx.x;
    if (e >= EE) return;
    const float* X = (sel ? g_o1 : g_s1) + b*SS*EE;
    const float* Y = (sel ? g_o2 : g_s2) + b*SS*EE;
    float a1 = 0.f, a2 = 0.f;
    for (int s = 0; s < SS; s++) { a1 += X[s*EE+e]; a2 += Y[s*EE+e]; }
    g_x[b*FCIN + slot*EE + e]     = a1*(1.f/SS);
    g_x[b*FCIN + (3+slot)*EE + e] = a2*(1.f/SS);
}

// ---------------- match-score: one CTA per batch, double-buffered ----------------
// mode=0: s1/s2 -> store A     mode=1: o1/o2 -> w1 (row sums), w2 (col sums)
__global__ __launch_bounds__(256) void k_match(int mode) {
    int b = blockIdx.x;
    const float* X = (mode ? g_o1 : g_s1) + b*SS*EE;
    const float* Y = (mode ? g_o2 : g_s2) + b*SS*EE;
    __shared__ float v1[SS], v2[SS], n1[SS], n2[SS];
    __shared__ float As[2][KT][SS+4];
    __shared__ float Bs[2][KT][SS+4];
    int tid = threadIdx.x;
    if (tid < SS) v1[tid] = g_v1[b*SS+tid];
    else          v2[tid-SS] = g_v2[b*SS + tid - SS];
    __syncthreads();

    int ty = tid >> 4, tx = tid & 15;
    int rown = tid & 127, which = tid >> 7;
    int rbase = tid >> 3, kkf = tid & 7;

    float mx[4], my[4];
#pragma unroll
    for (int j = 0; j < 4; j++) { mx[j] = v1[rbase+32*j]; my[j] = v2[rbase+32*j]; }

    float vx[4], vy[4];
    // fetch chunk 0
    {
        int k = kkf;
#pragma unroll
        for (int j = 0; j < 4; j++) {
            vx[j] = X[(rbase+32*j)*EE + k] * mx[j];
            vy[j] = Y[(rbase+32*j)*EE + k] * my[j];
        }
#pragma unroll
        for (int j = 0; j < 4; j++) { As[0][kkf][rbase+32*j] = vx[j]; Bs[0][kkf][rbase+32*j] = vy[j]; }
    }
    __syncthreads();

    float acc[8][8];
#pragma unroll
    for (int u = 0; u < 8; u++)
#pragma unroll
        for (int v = 0; v < 8; v++) acc[u][v] = 0.f;
    float nacc = 0.f;

    for (int c = 0; c < NCH; c++) {
        int cur = c & 1;
        if (c + 1 < NCH) {
            int k = (c+1)*KT + kkf;
            if (k < EE) {
#pragma unroll
                for (int j = 0; j < 4; j++) {
                    vx[j] = X[(rbase+32*j)*EE + k] * mx[j];
                    vy[j] = Y[(rbase+32*j)*EE + k] * my[j];
                }
            } else {
#pragma unroll
                for (int j = 0; j < 4; j++) { vx[j] = 0.f; vy[j] = 0.f; }
            }
        }
#pragma unroll
        for (int kk = 0; kk < KT; kk++) {
            float nv = which ? Bs[cur][kk][rown] : As[cur][kk][rown];
            nacc += nv*nv;
            float4 a0 = *(const float4*)&As[cur][kk][ty*8];
            float4 a1 = *(const float4*)&As[cur][kk][ty*8 + 4];
            float4 b0 = *(const float4*)&Bs[cur][kk][tx*8];
            float4 b1 = *(const float4*)&Bs[cur][kk][tx*8 + 4];
            float a[8]  = {a0.x,a0.y,a0.z,a0.w,a1.x,a1.y,a1.z,a1.w};
            float bb[8] = {b0.x,b0.y,b0.z,b0.w,b1.x,b1.y,b1.z,b1.w};
#pragma unroll
            for (int u = 0; u < 8; u++)
#pragma unroll
                for (int v = 0; v < 8; v++) acc[u][v] += a[u]*bb[v];
        }
        if (c + 1 < NCH) {
            int nb = cur ^ 1;
#pragma unroll
            for (int j = 0; j < 4; j++) { As[nb][kkf][rbase+32*j] = vx[j]; Bs[nb][kkf][rbase+32*j] = vy[j]; }
        }
        __syncthreads();
    }

    if (which) n2[rown] = nacc; else n1[rown] = nacc;
    __syncthreads();

    if (mode == 0) {
#pragma unroll
        for (int u = 0; u < 8; u++) {
            int r = ty*8 + u;
            float o[8];
#pragma unroll
            for (int v = 0; v < 8; v++) {
                int cc = tx*8 + v;
                float d2 = n1[r] + n2[cc] - 2.f*acc[u][v];
                float d = sqrtf(fmaxf(d2, 0.f));
                o[v] = 1.f/(1.f + d);
            }
            float* dst = &g_A[(b*SS + r)*SS + tx*8];
            *(float4*)dst       = make_float4(o[0],o[1],o[2],o[3]);
            *(float4*)(dst + 4) = make_float4(o[4],o[5],o[6],o[7]);
        }
    } else {
        float colsum[8];
#pragma unroll
        for (int v = 0; v < 8; v++) colsum[v] = 0.f;
#pragma unroll
        for (int u = 0; u < 8; u++) {
            int r = ty*8 + u;
            float rowsum = 0.f;
#pragma unroll
            for (int v = 0; v < 8; v++) {
                int cc = tx*8 + v;
                float d2 = n1[r] + n2[cc] - 2.f*acc[u][v];
                float d = sqrtf(fmaxf(d2, 0.f));
                float a = 1.f/(1.f + d);
                rowsum += a;
                colsum[v] += a;
            }
#pragma unroll
            for (int m = 8; m >= 1; m >>= 1)
                rowsum += __shfl_xor_sync(0xffffffffu, rowsum, m, 16);
            if (tx == 0) g_w1[b*SS + r] = rowsum;
        }
        // column sums via smem tree (reuse As region: needs 16*128 floats, As has 2112)
        float* colbuf = &As[0][0][0];
#pragma unroll
        for (int v = 0; v < 8; v++) colbuf[ty*SS + tx*8 + v] = colsum[v];
        __syncthreads();
        if (tid < SS) {
            float s = 0.f;
#pragma unroll
            for (int t = 0; t < 16; t++) s += colbuf[t*SS + tid];
            g_w2[b*SS + tid] = s;
        }
    }
}

// ---------------- f1 = A @ W[l], f2 = A^T @ W[l], double-buffered ----------------
__global__ __launch_bounds__(256) void k_fgemm(const float* __restrict__ W, int layer) {
    int b = blockIdx.x;
    int n0 = blockIdx.y * 64;
    int tflag = blockIdx.z;
    const float* Ab = g_A + b*SS*SS;
    const float* Wl = W + (size_t)layer*SS*EE;
    float* out = (tflag ? g_f2 : g_f1) + b*SS*EE;
    __shared__ float As[2][8][SS+4];
    __shared__ float Ws[2][8][68];
    int tid = threadIdx.x, ty = tid >> 4, tx = tid & 15;

    int rA0 = tid >> 3, kkA = tid & 7;     // non-transposed mapping
    int rT  = tid & 127, kkT0 = tid >> 7;  // transposed mapping

    float pa[4], pw[2];
    // fetch chunk 0
    if (!tflag) {
#pragma unroll
        for (int j = 0; j < 4; j++) pa[j] = Ab[(rA0+32*j)*SS + kkA];
    } else {
#pragma unroll
        for (int j = 0; j < 4; j++) pa[j] = Ab[(kkT0+2*j)*SS + rT];
    }
    {
        int i0 = tid, i1 = tid + 256;
        int kk0 = i0 >> 6, c0 = i0 & 63;
        int kk1 = i1 >> 6, c1 = i1 & 63;
        pw[0] = (n0+c0 < EE) ? Wl[kk0*EE + n0+c0] : 0.f;
        pw[1] = (n0+c1 < EE) ? Wl[kk1*EE + n0+c1] : 0.f;
    }
    if (!tflag) {
#pragma unroll
        for (int j = 0; j < 4; j++) As[0][kkA][rA0+32*j] = pa[j];
    } else {
#pragma unroll
        for (int j = 0; j < 4; j++) As[0][kkT0+2*j][rT] = pa[j];
    }
    {
        int i0 = tid, i1 = tid + 256;
        Ws[0][i0>>6][i0&63] = pw[0];
        Ws[0][i1>>6][i1&63] = pw[1];
    }
    __syncthreads();

    float acc[8][4];
#pragma unroll
    for (int u = 0; u < 8; u++)
#pragma unroll
        for (int v = 0; v < 4; v++) acc[u][v] = 0.f;

    const int nch = SS/8; // 16
    for (int c = 0; c < nch; c++) {
        int cur = c & 1;
        if (c + 1 < nch) {
            int k0 = (c+1)*8;
            if (!tflag) {
#pragma unroll
                for (int j = 0; j < 4; j++) pa[j] = Ab[(rA0+32*j)*SS + k0 + kkA];
            } else {
#pragma unroll
                for (int j = 0; j < 4; j++) pa[j] = Ab[(k0 + kkT0+2*j)*SS + rT];
            }
            int i0 = tid, i1 = tid + 256;
            int kk0 = i0 >> 6, c0 = i0 & 63;
            int kk1 = i1 >> 6, c1 = i1 & 63;
            pw[0] = (n0+c0 < EE) ? Wl[(k0+kk0)*EE + n0+c0] : 0.f;
            pw[1] = (n0+c1 < EE) ? Wl[(k0+kk1)*EE + n0+c1] : 0.f;
        }
#pragma unroll
        for (int kk = 0; kk < 8; kk++) {
            float4 a0 = *(const float4*)&As[cur][kk][ty*8];
            float4 a1 = *(const float4*)&As[cur][kk][ty*8 + 4];
            float4 w4 = *(const float4*)&Ws[cur][kk][tx*4];
            float a[8] = {a0.x,a0.y,a0.z,a0.w,a1.x,a1.y,a1.z,a1.w};
            float w[4] = {w4.x,w4.y,w4.z,w4.w};
#pragma unroll
            for (int u = 0; u < 8; u++)
#pragma unroll
                for (int v = 0; v < 4; v++) acc[u][v] += a[u]*w[v];
        }
        if (c + 1 < nch) {
            int nb = cur ^ 1;
            if (!tflag) {
#pragma unroll
                for (int j = 0; j < 4; j++) As[nb][kkA][rA0+32*j] = pa[j];
            } else {
#pragma unroll
                for (int j = 0; j < 4; j++) As[nb][kkT0+2*j][rT] = pa[j];
            }
            int i0 = tid, i1 = tid + 256;
            Ws[nb][i0>>6][i0&63] = pw[0];
            Ws[nb][i1>>6][i1&63] = pw[1];
        }
        __syncthreads();
    }
#pragma unroll
    for (int u = 0; u < 8; u++) {
        int r = ty*8 + u;
        int cc = n0 + tx*4;
        if (cc + 3 < EE) {
            *(float4*)&out[r*EE + cc] = make_float4(acc[u][0],acc[u][1],acc[u][2],acc[u][3]);
        } else {
#pragma unroll
            for (int v = 0; v < 4; v++)
                if (cc + v < EE) out[r*EE + cc + v] = acc[u][v];
        }
    }
}

// ---------------- conv 2in->1out 3x3 + tanh, chunked rows ----------------
// grid (B, 8, 2), block 256; chunk of 16 rows + 2 halo staged in smem
__global__ __launch_bounds__(256) void k_conv(const float* __restrict__ cw,
                                              const float* __restrict__ cb, int layer) {
    int b = blockIdx.x, ch = blockIdx.y, pair = blockIdx.z;
    int s0 = ch * CROWS;
    const float* X0 = (pair ? g_s2 : g_s1) + b*SS*EE;
    const float* X1 = (pair ? g_f2 : g_f1) + b*SS*EE;
    float* O = (pair ? g_o2 : g_o1) + b*SS*EE;
    __shared__ float xs[2][CROWS+2][EE+2];
    __shared__ float w[18];
    int tid = threadIdx.x;
    if (tid < 18) w[tid] = cw[layer*18 + tid];
    if (tid < 2*(CROWS+2)*2) {   // 72 pad entries
        int c = tid / (2*(CROWS+2));
        int rem = tid % (2*(CROWS+2));
        int j = rem >> 1, side = rem & 1;
        xs[c][j][side ? EE+1 : 0] = 0.f;
    }
    for (int i = tid; i < 2*(CROWS+2)*(EE/4); i += 256) {
        int c = i / ((CROWS+2)*(EE/4));
        int rem = i % ((CROWS+2)*(EE/4));
        int j = rem / (EE/4), q = rem % (EE/4);
        int srow = s0 + j - 1;
        float4 val = make_float4(0.f,0.f,0.f,0.f);
        if (srow >= 0 && srow < SS)
            val = *(const float4*)((c ? X1 : X0) + srow*EE + q*4);
        float* dptr = &xs[c][j][q*4 + 1];
        dptr[0]=val.x; dptr[1]=val.y; dptr[2]=val.z; dptr[3]=val.w;
    }
    float bias = cb[layer];
    __syncthreads();
    for (int i = tid; i < CROWS*EE; i += 256) {
        int r = i / EE, e = i % EE;
        float acc = bias;
#pragma unroll
        for (int c = 0; c < 2; c++)
#pragma unroll
            for (int kh = 0; kh < 3; kh++)
#pragma unroll
                for (int kw = 0; kw < 3; kw++)
                    acc += w[c*9 + kh*3 + kw] * xs[c][r+kh][e + kw];
        O[(s0+r)*EE + e] = tanh_fast(acc);
    }
}

// ---------------- weighted avg-pool3 + residual update, rolling regs ----------------
// grid (B, 8, 2), block 128
__global__ __launch_bounds__(128) void k_pool() {
    int b = blockIdx.x, ch = blockIdx.y, pair = blockIdx.z;
    int s0 = ch * CROWS;
    const float* O = (pair ? g_o2 : g_o1) + b*SS*EE;
    float* Sx = (pair ? g_s2 : g_s1) + b*SS*EE;
    const float* wv = (pair ? g_w2 : g_w1) + b*SS;
    __shared__ float w[CROWS+2];
    if (threadIdx.x < CROWS+2) {
        int s = s0 + (int)threadIdx.x - 1;
        w[threadIdx.x] = (s >= 0 && s < SS) ? wv[s] : 0.f;
    }
    __syncthreads();
    for (int e = threadIdx.x; e < EE; e += 128) {
        float a = (s0 > 0) ? O[(s0-1)*EE + e] * w[0] : 0.f;
        float bmid = O[s0*EE + e] * w[1];
#pragma unroll
        for (int i = 0; i < CROWS; i++) {
            int s = s0 + i;
            float cnext = (s+1 < SS) ? O[(s+1)*EE + e] * w[i+2] : 0.f;
            Sx[s*EE + e] += (a + bmid + cnext) * (1.f/3.f);
            a = bmid; bmid = cnext;
        }
    }
}

// ---------------- fc1 GEMM: [512,1800] @ [1800,300]^T -> g_h ----------------
__global__ __launch_bounds__(256) void k_fc1(const float* __restrict__ fw) {
    int m0 = blockIdx.x * 64, n0 = blockIdx.y * 64;
    __shared__ float Xs[8][68];
    __shared__ float Ws[8][68];
    int tid = threadIdx.x, ty = tid >> 4, tx = tid & 15;
    float acc[4][4];
#pragma unroll
    for (int u = 0; u < 4; u++)
#pragma unroll
        for (int v = 0; v < 4; v++) acc[u][v] = 0.f;

    for (int k0 = 0; k0 < FCIN; k0 += 8) {
        __syncthreads();
#pragma unroll 2
        for (int i = tid; i < 512; i += 256) {
            int r = i >> 3, kk = i & 7;
            Xs[kk][r] = g_x[(m0 + r)*FCIN + k0 + kk];
            int n = n0 + r;
            Ws[kk][r] = (n < HH) ? fw[n*FCIN + k0 + kk] : 0.f;
        }
        __syncthreads();
#pragma unroll
        for (int kk = 0; kk < 8; kk++) {
            float4 xa = *(const float4*)&Xs[kk][ty*4];
            float4 wb = *(const float4*)&Ws[kk][tx*4];
            float xv[4] = {xa.x, xa.y, xa.z, xa.w};
            float wvv[4] = {wb.x, wb.y, wb.z, wb.w};
#pragma unroll
            for (int u = 0; u < 4; u++)
#pragma unroll
                for (int v = 0; v < 4; v++) acc[u][v] += xv[u]*wvv[v];
        }
    }
#pragma unroll
    for (int u = 0; u < 4; u++) {
        int m = m0 + ty*4 + u;
#pragma unroll
        for (int v = 0; v < 4; v++) {
            int n = n0 + tx*4 + v;
            if (n < HH) g_h[m*HH + n] = acc[u][v];
        }
    }
}

// ---------------- LN + relu + fc2 + softmax ----------------
__device__ __forceinline__ float block_reduce512(float v, float* red) {
    int tid = threadIdx.x;
    red[tid] = v;
    __syncthreads();
    for (int off = 256; off > 0; off >>= 1) {
        if (tid < off) red[tid] += red[tid + off];
        __syncthreads();
    }
    float r = red[0];
    __syncthreads();
    return r;
}

__global__ __launch_bounds__(512) void k_head(const float* __restrict__ fc1b,
                                              const float* __restrict__ lng,
                                              const float* __restrict__ lnb,
                                              const float* __restrict__ fc2w,
                                              const float* __restrict__ fc2b,
                                              float* __restrict__ out) {
    int b = blockIdx.x, tid = threadIdx.x;
    __shared__ float red[512];
    bool act = tid < HH;
    float h = act ? (g_h[b*HH + tid] + fc1b[tid]) : 0.f;
    float mu = block_reduce512(h, red) * (1.f/HH);
    float d = act ? (h - mu) : 0.f;
    float var = block_reduce512(d*d, red) * (1.f/HH);
    float hn = 0.f;
    if (act) {
        hn = d * rsqrtf(var + 1e-5f) * lng[tid] + lnb[tid];
        hn = fmaxf(hn, 0.f);
    }
    float o0 = block_reduce512(act ? hn*fc2w[tid]      : 0.f, red);
    float o1 = block_reduce512(act ? hn*fc2w[HH + tid] : 0.f, red);
    if (tid == 0) {
        o0 += fc2b[0];
        o1 += fc2b[1];
        out[b*2 + 0] = o0;
        out[b*2 + 1] = o1;
        float m = fmaxf(o0, o1);
        float e0 = expf(o0 - m), e1 = expf(o1 - m);
        float inv = 1.f/(e0 + e1);
        out[BB*2 + b*2 + 0] = e0*inv;
        out[BB*2 + b*2 + 1] = e1*inv;
    }
}

// ---------------- launch ----------------
extern "C" void kernel_launch(void* const* d_in, const int* in_sizes, int n_in,
                              void* d_out, int out_size) {
    (void)in_sizes; (void)n_in; (void)out_size;
    const int*   seq1 = (const int*)d_in[0];
    const int*   seq2 = (const int*)d_in[1];
    const float* emb  = (const float*)d_in[2];
    const float* W    = (const float*)d_in[3];
    const float* cw   = (const float*)d_in[4];
    const float* cb   = (const float*)d_in[5];
    const float* fc1w = (const float*)d_in[6];
    const float* fc1b = (const float*)d_in[7];
    const float* lng  = (const float*)d_in[8];
    const float* lnb  = (const float*)d_in[9];
    const float* fc2w = (const float*)d_in[10];
    const float* fc2b = (const float*)d_in[11];
    float* out = (float*)d_out;

    k_gather<<<BB, 256>>>(seq1, seq2, emb);
    k_mean<<<dim3(BB, 3), 128>>>(0, 0);
    for (int l = 0; l < LL; l++) {
        k_match<<<BB, 256>>>(0);
        k_fgemm<<<dim3(BB, 5, 2), 256>>>(W, l);
        k_conv<<<dim3(BB, 8, 2), 256>>>(cw, cb, l);
        k_mean<<<dim3(BB, 3), 128>>>(1, 1 + l);
        k_match<<<BB, 256>>>(1);
        k_pool<<<dim3(BB, 8, 2), 128>>>();
    }
    k_fc1<<<dim3(8, 5), 256>>>(fc1w);
    k_head<<<BB, 512>>>(fc1b, lng, lnb, fc2w, fc2b, out);
}

// round 3
// speedup vs baseline: 1.9716x; 1.4614x over previous
#include <cuda_runtime.h>
#include <math.h>
#include <stdint.h>

#define BB 512
#define SS 128
#define EE 300
#define LL 2
#define HH 300
#define FCIN 1800   // E*(1+L)*2
#define CROWS 16

// ---------------- device scratch (no allocation allowed) ----------------
__device__ float g_s1[BB*SS*EE];
__device__ float g_s2[BB*SS*EE];
__device__ float g_f1[BB*SS*EE];
__device__ float g_f2[BB*SS*EE];
__device__ float g_o1[BB*SS*EE];
__device__ float g_o2[BB*SS*EE];
__device__ float g_A [BB*SS*SS];
__device__ float g_w1[BB*SS];
__device__ float g_w2[BB*SS];
__device__ float g_v1[BB*SS];
__device__ float g_v2[BB*SS];
__device__ float g_x [BB*FCIN];
__device__ float g_h [BB*HH];

__device__ __forceinline__ float tanh_fast(float x) {
    float r; asm("tanh.approx.f32 %0, %1;" : "=f"(r) : "f"(x)); return r;
}
__device__ __forceinline__ uint32_t to_tf32(float x) {
    uint32_t r; asm("cvt.rna.tf32.f32 %0, %1;" : "=r"(r) : "f"(x)); return r;
}
#define MMA_TF32(C, A, B) \
    asm volatile("mma.sync.aligned.m16n8k8.row.col.f32.tf32.tf32.f32 " \
        "{%0,%1,%2,%3}, {%4,%5,%6,%7}, {%8,%9}, {%0,%1,%2,%3};" \
        : "+f"((C)[0]), "+f"((C)[1]), "+f"((C)[2]), "+f"((C)[3]) \
        : "r"((A)[0]), "r"((A)[1]), "r"((A)[2]), "r"((A)[3]), \
          "r"((B)[0]), "r"((B)[1]))

// ---------------- embedding gather (+ valid masks), float4 ----------------
__global__ __launch_bounds__(256) void k_gather(const int* __restrict__ seq1,
                                                const int* __restrict__ seq2,
                                                const float* __restrict__ emb) {
    int b = blockIdx.x;
    int warp = threadIdx.x >> 5, lane = threadIdx.x & 31;
    for (int i = threadIdx.x; i < SS; i += 256) {
        g_v1[b*SS+i] = (seq1[b*SS+i] != 0) ? 1.f : 0.f;
        g_v2[b*SS+i] = (seq2[b*SS+i] != 0) ? 1.f : 0.f;
    }
    for (int idx = warp; idx < 2*SS; idx += 8) {
        int s = idx >> 1, sel = idx & 1;
        int tok = sel ? seq2[b*SS+s] : seq1[b*SS+s];
        const float4* src = (const float4*)(emb + (long)tok*EE);
        float4* dst = (float4*)((sel ? g_s2 : g_s1) + (b*SS+s)*EE);
        for (int j = lane; j < EE/4; j += 32) dst[j] = src[j];
    }
}

// ---------------- mean over S of s1/s2 -> g_x slot 0 ----------------
__global__ void k_mean0() {
    int b = blockIdx.x;
    int e = blockIdx.y*128 + threadIdx.x;
    if (e >= EE) return;
    const float* X = g_s1 + b*SS*EE;
    const float* Y = g_s2 + b*SS*EE;
    float a1 = 0.f, a2 = 0.f;
    for (int s = 0; s < SS; s++) { a1 += X[s*EE+e]; a2 += Y[s*EE+e]; }
    g_x[b*FCIN + e]        = a1*(1.f/SS);
    g_x[b*FCIN + 3*EE + e] = a2*(1.f/SS);
}

// ---------------- zero mean slots for layer l (conv accumulates atomically) ----
__global__ void k_zx(int l) {
    int i = blockIdx.x*256 + threadIdx.x;
    if (i >= BB*2*EE) return;
    int b = i / (2*EE);
    int r = i % (2*EE);
    int half = r / EE, e = r % EE;
    int slot = half ? (4+l) : (1+l);
    g_x[b*FCIN + slot*EE + e] = 0.f;
}

// ---------------- match-score, tensor-core tf32 ----------------
// mode=0: s1/s2 -> store A     mode=1: o1/o2 -> w1 (row sums), w2 (col sums)
// one CTA per batch; 256 threads = 8 warps, warp tile 64x32
#define MPAD 36
#define MCH 10      // ceil(300/32)
__global__ __launch_bounds__(256) void k_match(int mode) {
    extern __shared__ float sm[];
    float* Xs = sm;                       // [2][128][36]
    float* Ys = Xs + 2*SS*MPAD;           // [2][128][36]
    float* n1s = Ys + 2*SS*MPAD;          // [128]
    float* n2s = n1s + SS;                // [128]
    float* rowbuf = n2s + SS;             // [4][128]
    float* colbuf = rowbuf + 4*SS;        // [2][128]

    int b = blockIdx.x;
    const float* X = (mode ? g_o1 : g_s1) + b*SS*EE;
    const float* Y = (mode ? g_o2 : g_s2) + b*SS*EE;
    int tid = threadIdx.x;
    int lane = tid & 31, wid = tid >> 5;
    int g = lane >> 2, tig = lane & 3;
    int wm = wid & 1, wn = wid >> 1;

    // loader mapping: thread -> (row, half-of-32-cols)
    int lr = tid >> 1, lh = tid & 1;
    const float* Xr = X + lr*EE + lh*16;
    const float* Yr = Y + lr*EE + lh*16;
    float mvx = g_v1[b*SS + lr];
    float mvy = g_v2[b*SS + lr];
    float nx = 0.f, ny = 0.f;
    float4 vx[4], vy[4];

#define FETCH(c) do { \
    int kb = (c)*32; \
    _Pragma("unroll") for (int j = 0; j < 4; j++) { \
        int k = kb + lh*16 + 4*j; \
        if (k < EE) { vx[j] = *(const float4*)(Xr + kb + 4*j); \
                      vy[j] = *(const float4*)(Yr + kb + 4*j); } \
        else { vx[j] = make_float4(0.f,0.f,0.f,0.f); vy[j] = vx[j]; } \
    } } while(0)

#define STBUF(buf) do { \
    float* xd = Xs + (buf)*SS*MPAD + lr*MPAD + lh*16; \
    float* yd = Ys + (buf)*SS*MPAD + lr*MPAD + lh*16; \
    _Pragma("unroll") for (int j = 0; j < 4; j++) { \
        float x0=vx[j].x*mvx, x1=vx[j].y*mvx, x2=vx[j].z*mvx, x3=vx[j].w*mvx; \
        float y0=vy[j].x*mvy, y1=vy[j].y*mvy, y2=vy[j].z*mvy, y3=vy[j].w*mvy; \
        nx += x0*x0+x1*x1+x2*x2+x3*x3; \
        ny += y0*y0+y1*y1+y2*y2+y3*y3; \
        ((uint32_t*)xd)[4*j+0]=to_tf32(x0); ((uint32_t*)xd)[4*j+1]=to_tf32(x1); \
        ((uint32_t*)xd)[4*j+2]=to_tf32(x2); ((uint32_t*)xd)[4*j+3]=to_tf32(x3); \
        ((uint32_t*)yd)[4*j+0]=to_tf32(y0); ((uint32_t*)yd)[4*j+1]=to_tf32(y1); \
        ((uint32_t*)yd)[4*j+2]=to_tf32(y2); ((uint32_t*)yd)[4*j+3]=to_tf32(y3); \
    } } while(0)

    float acc[4][4][4];
#pragma unroll
    for (int mt = 0; mt < 4; mt++)
#pragma unroll
        for (int nt = 0; nt < 4; nt++)
#pragma unroll
            for (int q = 0; q < 4; q++) acc[mt][nt][q] = 0.f;

    FETCH(0); STBUF(0);
    __syncthreads();

    for (int c = 0; c < MCH; c++) {
        int cur = c & 1;
        if (c + 1 < MCH) FETCH(c+1);
        const uint32_t* xb = (const uint32_t*)(Xs + cur*SS*MPAD);
        const uint32_t* yb = (const uint32_t*)(Ys + cur*SS*MPAD);
#pragma unroll
        for (int ks = 0; ks < 4; ks++) {
            int kk = ks*8;
            uint32_t a[4][4], bf[4][2];
#pragma unroll
            for (int mt = 0; mt < 4; mt++) {
                int row = wm*64 + mt*16 + g;
                a[mt][0] = xb[row*MPAD + kk + tig];
                a[mt][1] = xb[(row+8)*MPAD + kk + tig];
                a[mt][2] = xb[row*MPAD + kk + tig + 4];
                a[mt][3] = xb[(row+8)*MPAD + kk + tig + 4];
            }
#pragma unroll
            for (int nt = 0; nt < 4; nt++) {
                int cr = wn*32 + nt*8 + g;
                bf[nt][0] = yb[cr*MPAD + kk + tig];
                bf[nt][1] = yb[cr*MPAD + kk + tig + 4];
            }
#pragma unroll
            for (int mt = 0; mt < 4; mt++)
#pragma unroll
                for (int nt = 0; nt < 4; nt++)
                    MMA_TF32(acc[mt][nt], a[mt], bf[nt]);
        }
        if (c + 1 < MCH) STBUF(cur ^ 1);
        __syncthreads();
    }

    // norms: pair-reduce
    nx += __shfl_xor_sync(0xffffffffu, nx, 1);
    ny += __shfl_xor_sync(0xffffffffu, ny, 1);
    if (lh == 0) { n1s[lr] = nx; n2s[lr] = ny; }
    __syncthreads();

    if (mode == 0) {
        float* Ao = g_A + b*SS*SS;
#pragma unroll
        for (int mt = 0; mt < 4; mt++) {
            int row = wm*64 + mt*16 + g;
            float nr0 = n1s[row], nr1 = n1s[row+8];
#pragma unroll
            for (int nt = 0; nt < 4; nt++) {
                int col = wn*32 + nt*8 + 2*tig;
                float nc0 = n2s[col], nc1 = n2s[col+1];
                float d00 = sqrtf(fmaxf(nr0 + nc0 - 2.f*acc[mt][nt][0], 0.f));
                float d01 = sqrtf(fmaxf(nr0 + nc1 - 2.f*acc[mt][nt][1], 0.f));
                float d10 = sqrtf(fmaxf(nr1 + nc0 - 2.f*acc[mt][nt][2], 0.f));
                float d11 = sqrtf(fmaxf(nr1 + nc1 - 2.f*acc[mt][nt][3], 0.f));
                *(float2*)(Ao + row*SS + col)     = make_float2(1.f/(1.f+d00), 1.f/(1.f+d01));
                *(float2*)(Ao + (row+8)*SS + col) = make_float2(1.f/(1.f+d10), 1.f/(1.f+d11));
            }
        }
    } else {
        float cs0[4], cs1[4];
#pragma unroll
        for (int nt = 0; nt < 4; nt++) { cs0[nt] = 0.f; cs1[nt] = 0.f; }
#pragma unroll
        for (int mt = 0; mt < 4; mt++) {
            int row = wm*64 + mt*16 + g;
            float nr0 = n1s[row], nr1 = n1s[row+8];
            float rlo = 0.f, rhi = 0.f;
#pragma unroll
            for (int nt = 0; nt < 4; nt++) {
                int col = wn*32 + nt*8 + 2*tig;
                float nc0 = n2s[col], nc1 = n2s[col+1];
                float a00 = 1.f/(1.f + sqrtf(fmaxf(nr0 + nc0 - 2.f*acc[mt][nt][0], 0.f)));
                float a01 = 1.f/(1.f + sqrtf(fmaxf(nr0 + nc1 - 2.f*acc[mt][nt][1], 0.f)));
                float a10 = 1.f/(1.f + sqrtf(fmaxf(nr1 + nc0 - 2.f*acc[mt][nt][2], 0.f)));
                float a11 = 1.f/(1.f + sqrtf(fmaxf(nr1 + nc1 - 2.f*acc[mt][nt][3], 0.f)));
                rlo += a00 + a01;
                rhi += a10 + a11;
                cs0[nt] += a00 + a10;
                cs1[nt] += a01 + a11;
            }
            rlo += __shfl_xor_sync(0xffffffffu, rlo, 1);
            rlo += __shfl_xor_sync(0xffffffffu, rlo, 2);
            rhi += __shfl_xor_sync(0xffffffffu, rhi, 1);
            rhi += __shfl_xor_sync(0xffffffffu, rhi, 2);
            if (tig == 0) {
                rowbuf[wn*SS + row]   = rlo;
                rowbuf[wn*SS + row+8] = rhi;
            }
        }
#pragma unroll
        for (int nt = 0; nt < 4; nt++) {
            float c0 = cs0[nt], c1 = cs1[nt];
            c0 += __shfl_xor_sync(0xffffffffu, c0, 4);
            c0 += __shfl_xor_sync(0xffffffffu, c0, 8);
            c0 += __shfl_xor_sync(0xffffffffu, c0, 16);
            c1 += __shfl_xor_sync(0xffffffffu, c1, 4);
            c1 += __shfl_xor_sync(0xffffffffu, c1, 8);
            c1 += __shfl_xor_sync(0xffffffffu, c1, 16);
            if (g == 0) {
                int col = wn*32 + nt*8 + 2*tig;
                colbuf[wm*SS + col]     = c0;
                colbuf[wm*SS + col + 1] = c1;
            }
        }
        __syncthreads();
        if (tid < SS) {
            g_w1[b*SS + tid] = rowbuf[tid] + rowbuf[SS+tid] + rowbuf[2*SS+tid] + rowbuf[3*SS+tid];
            g_w2[b*SS + tid] = colbuf[tid] + colbuf[SS+tid];
        }
    }
#undef FETCH
#undef STBUF
}

// ---------------- f1 = A@W, f2 = A^T@W in ONE CTA, tensor cores ----------------
// grid (B, 5); 8 warps: warps 0-3 -> f1 rows 32w, warps 4-7 -> f2
#define FPAD 132
__global__ __launch_bounds__(256) void k_fgemm(const float* __restrict__ W, int layer) {
    extern __shared__ float sm[];
    uint32_t* As = (uint32_t*)sm;              // [128][132]
    uint32_t* Ws = As + SS*FPAD;               // [64][132] (transposed: Ws[n][k])

    int b = blockIdx.x;
    int n0 = blockIdx.y * 64;
    const float* Ab = g_A + b*SS*SS;
    const float* Wl = W + (size_t)layer*SS*EE;
    int tid = threadIdx.x;
    int lane = tid & 31, wid = tid >> 5;
    int g = lane >> 2, tig = lane & 3;
    int half = wid >> 2, wm = wid & 3;

    // load A (128x128) -> tf32 smem
    {
        int r = tid >> 1, h = tid & 1;
        const float* src = Ab + r*SS + h*64;
        uint32_t* dst = As + r*FPAD + h*64;
#pragma unroll
        for (int q = 0; q < 16; q++) {
            float4 v = *(const float4*)(src + 4*q);
            dst[4*q+0] = to_tf32(v.x); dst[4*q+1] = to_tf32(v.y);
            dst[4*q+2] = to_tf32(v.z); dst[4*q+3] = to_tf32(v.w);
        }
    }
    // load W tile transposed: Ws[n][k]
    {
        int k = tid >> 1, h = tid & 1;
#pragma unroll
        for (int q = 0; q < 8; q++) {
            int n = h*32 + 4*q;
            float4 v = make_float4(0.f,0.f,0.f,0.f);
            if (n0 + n < EE) v = *(const float4*)(Wl + k*EE + n0 + n);
            Ws[(n+0)*FPAD + k] = to_tf32(v.x);
            Ws[(n+1)*FPAD + k] = to_tf32(v.y);
            Ws[(n+2)*FPAD + k] = to_tf32(v.z);
            Ws[(n+3)*FPAD + k] = to_tf32(v.w);
        }
    }
    __syncthreads();

    float acc[2][8][4];
#pragma unroll
    for (int mt = 0; mt < 2; mt++)
#pragma unroll
        for (int nt = 0; nt < 8; nt++)
#pragma unroll
            for (int q = 0; q < 4; q++) acc[mt][nt][q] = 0.f;

#pragma unroll 4
    for (int ks = 0; ks < 16; ks++) {
        int kk = ks*8;
        uint32_t a[2][4], bf[8][2];
#pragma unroll
        for (int mt = 0; mt < 2; mt++) {
            int row = wm*32 + mt*16 + g;
            if (half == 0) {
                a[mt][0] = As[row*FPAD + kk + tig];
                a[mt][1] = As[(row+8)*FPAD + kk + tig];
                a[mt][2] = As[row*FPAD + kk + tig + 4];
                a[mt][3] = As[(row+8)*FPAD + kk + tig + 4];
            } else {
                a[mt][0] = As[(kk+tig)*FPAD + row];
                a[mt][1] = As[(kk+tig)*FPAD + row + 8];
                a[mt][2] = As[(kk+tig+4)*FPAD + row];
                a[mt][3] = As[(kk+tig+4)*FPAD + row + 8];
            }
        }
#pragma unroll
        for (int nt = 0; nt < 8; nt++) {
            int cn = nt*8 + g;
            bf[nt][0] = Ws[cn*FPAD + kk + tig];
            bf[nt][1] = Ws[cn*FPAD + kk + tig + 4];
        }
#pragma unroll
        for (int mt = 0; mt < 2; mt++)
#pragma unroll
            for (int nt = 0; nt < 8; nt++)
                MMA_TF32(acc[mt][nt], a[mt], bf[nt]);
    }

    float* out = (half ? g_f2 : g_f1) + b*SS*EE;
#pragma unroll
    for (int mt = 0; mt < 2; mt++) {
        int row = wm*32 + mt*16 + g;
#pragma unroll
        for (int nt = 0; nt < 8; nt++) {
            int col = n0 + nt*8 + 2*tig;
            if (col < EE) {
                *(float2*)(out + row*EE + col)     = make_float2(acc[mt][nt][0], acc[mt][nt][1]);
                *(float2*)(out + (row+8)*EE + col) = make_float2(acc[mt][nt][2], acc[mt][nt][3]);
            }
        }
    }
}

// ---------------- conv 2in->1out 3x3 + tanh + fused mean accumulation ----------------
// grid (B, 8, 2), block 256; dynamic smem
__global__ __launch_bounds__(256) void k_conv(const float* __restrict__ cw,
                                              const float* __restrict__ cb, int layer) {
    extern __shared__ float sm[];
    float* xs = sm;                       // [2][18][302]
    float* os = xs + 2*(CROWS+2)*(EE+2);  // [16][300]
    float* w  = os + CROWS*EE;            // [18]

    int b = blockIdx.x, ch = blockIdx.y, pair = blockIdx.z;
    int s0 = ch * CROWS;
    const float* X0 = (pair ? g_s2 : g_s1) + b*SS*EE;
    const float* X1 = (pair ? g_f2 : g_f1) + b*SS*EE;
    float* O = (pair ? g_o2 : g_o1) + b*SS*EE;
    int tid = threadIdx.x;
    if (tid < 18) w[tid] = cw[layer*18 + tid];
    if (tid < 2*(CROWS+2)*2) {
        int c = tid / (2*(CROWS+2));
        int rem = tid % (2*(CROWS+2));
        int j = rem >> 1, side = rem & 1;
        xs[(c*(CROWS+2) + j)*(EE+2) + (side ? EE+1 : 0)] = 0.f;
    }
    for (int i = tid; i < 2*(CROWS+2)*(EE/4); i += 256) {
        int c = i / ((CROWS+2)*(EE/4));
        int rem = i % ((CROWS+2)*(EE/4));
        int j = rem / (EE/4), q = rem % (EE/4);
        int srow = s0 + j - 1;
        float4 val = make_float4(0.f,0.f,0.f,0.f);
        if (srow >= 0 && srow < SS)
            val = *(const float4*)((c ? X1 : X0) + srow*EE + q*4);
        float* dptr = &xs[(c*(CROWS+2) + j)*(EE+2) + q*4 + 1];
        dptr[0]=val.x; dptr[1]=val.y; dptr[2]=val.z; dptr[3]=val.w;
    }
    float bias = cb[layer];
    __syncthreads();
    for (int i = tid; i < CROWS*EE; i += 256) {
        int r = i / EE, e = i % EE;
        float acc = bias;
#pragma unroll
        for (int c = 0; c < 2; c++)
#pragma unroll
            for (int kh = 0; kh < 3; kh++)
#pragma unroll
                for (int kw = 0; kw < 3; kw++)
                    acc += w[c*9 + kh*3 + kw] * xs[(c*(CROWS+2) + r+kh)*(EE+2) + e + kw];
        float t = tanh_fast(acc);
        O[(s0+r)*EE + e] = t;
        os[r*EE + e] = t;
    }
    __syncthreads();
    int slot = (pair ? 4 : 1) + layer;
    for (int e = tid; e < EE; e += 256) {
        float s = 0.f;
#pragma unroll
        for (int r = 0; r < CROWS; r++) s += os[r*EE + e];
        atomicAdd(&g_x[b*FCIN + slot*EE + e], s*(1.f/SS));
    }
}

// ---------------- weighted avg-pool3 + residual update, rolling regs ----------------
__global__ __launch_bounds__(128) void k_pool() {
    int b = blockIdx.x, ch = blockIdx.y, pair = blockIdx.z;
    int s0 = ch * CROWS;
    const float* O = (pair ? g_o2 : g_o1) + b*SS*EE;
    float* Sx = (pair ? g_s2 : g_s1) + b*SS*EE;
    const float* wv = (pair ? g_w2 : g_w1) + b*SS;
    __shared__ float w[CROWS+2];
    if (threadIdx.x < CROWS+2) {
        int s = s0 + (int)threadIdx.x - 1;
        w[threadIdx.x] = (s >= 0 && s < SS) ? wv[s] : 0.f;
    }
    __syncthreads();
    for (int e = threadIdx.x; e < EE; e += 128) {
        float a = (s0 > 0) ? O[(s0-1)*EE + e] * w[0] : 0.f;
        float bmid = O[s0*EE + e] * w[1];
#pragma unroll
        for (int i = 0; i < CROWS; i++) {
            int s = s0 + i;
            float cnext = (s+1 < SS) ? O[(s+1)*EE + e] * w[i+2] : 0.f;
            Sx[s*EE + e] += (a + bmid + cnext) * (1.f/3.f);
            a = bmid; bmid = cnext;
        }
    }
}

// ---------------- fc1 GEMM: [512,1800] @ [1800,300]^T -> g_h ----------------
__global__ __launch_bounds__(256) void k_fc1(const float* __restrict__ fw) {
    int m0 = blockIdx.x * 64, n0 = blockIdx.y * 64;
    __shared__ float Xs[8][68];
    __shared__ float Ws[8][68];
    int tid = threadIdx.x, ty = tid >> 4, tx = tid & 15;
    float acc[4][4];
#pragma unroll
    for (int u = 0; u < 4; u++)
#pragma unroll
        for (int v = 0; v < 4; v++) acc[u][v] = 0.f;

    for (int k0 = 0; k0 < FCIN; k0 += 8) {
        __syncthreads();
#pragma unroll 2
        for (int i = tid; i < 512; i += 256) {
            int r = i >> 3, kk = i & 7;
            Xs[kk][r] = g_x[(m0 + r)*FCIN + k0 + kk];
            int n = n0 + r;
            Ws[kk][r] = (n < HH) ? fw[n*FCIN + k0 + kk] : 0.f;
        }
        __syncthreads();
#pragma unroll
        for (int kk = 0; kk < 8; kk++) {
            float4 xa = *(const float4*)&Xs[kk][ty*4];
            float4 wb = *(const float4*)&Ws[kk][tx*4];
            float xv[4] = {xa.x, xa.y, xa.z, xa.w};
            float wvv[4] = {wb.x, wb.y, wb.z, wb.w};
#pragma unroll
            for (int u = 0; u < 4; u++)
#pragma unroll
                for (int v = 0; v < 4; v++) acc[u][v] += xv[u]*wvv[v];
        }
    }
#pragma unroll
    for (int u = 0; u < 4; u++) {
        int m = m0 + ty*4 + u;
#pragma unroll
        for (int v = 0; v < 4; v++) {
            int n = n0 + tx*4 + v;
            if (n < HH) g_h[m*HH + n] = acc[u][v];
        }
    }
}

// ---------------- LN + relu + fc2 + softmax ----------------
__device__ __forceinline__ float block_reduce512(float v, float* red) {
    int tid = threadIdx.x;
    red[tid] = v;
    __syncthreads();
    for (int off = 256; off > 0; off >>= 1) {
        if (tid < off) red[tid] += red[tid + off];
        __syncthreads();
    }
    float r = red[0];
    __syncthreads();
    return r;
}

__global__ __launch_bounds__(512) void k_head(const float* __restrict__ fc1b,
                                              const float* __restrict__ lng,
                                              const float* __restrict__ lnb,
                                              const float* __restrict__ fc2w,
                                              const float* __restrict__ fc2b,
                                              float* __restrict__ out) {
    int b = blockIdx.x, tid = threadIdx.x;
    __shared__ float red[512];
    bool act = tid < HH;
    float h = act ? (g_h[b*HH + tid] + fc1b[tid]) : 0.f;
    float mu = block_reduce512(h, red) * (1.f/HH);
    float d = act ? (h - mu) : 0.f;
    float var = block_reduce512(d*d, red) * (1.f/HH);
    float hn = 0.f;
    if (act) {
        hn = d * rsqrtf(var + 1e-5f) * lng[tid] + lnb[tid];
        hn = fmaxf(hn, 0.f);
    }
    float o0 = block_reduce512(act ? hn*fc2w[tid]      : 0.f, red);
    float o1 = block_reduce512(act ? hn*fc2w[HH + tid] : 0.f, red);
    if (tid == 0) {
        o0 += fc2b[0];
        o1 += fc2b[1];
        out[b*2 + 0] = o0;
        out[b*2 + 1] = o1;
        float m = fmaxf(o0, o1);
        float e0 = expf(o0 - m), e1 = expf(o1 - m);
        float inv = 1.f/(e0 + e1);
        out[BB*2 + b*2 + 0] = e0*inv;
        out[BB*2 + b*2 + 1] = e1*inv;
    }
}

// ---------------- launch ----------------
extern "C" void kernel_launch(void* const* d_in, const int* in_sizes, int n_in,
                              void* d_out, int out_size) {
    (void)in_sizes; (void)n_in; (void)out_size;
    const int*   seq1 = (const int*)d_in[0];
    const int*   seq2 = (const int*)d_in[1];
    const float* emb  = (const float*)d_in[2];
    const float* W    = (const float*)d_in[3];
    const float* cw   = (const float*)d_in[4];
    const float* cb   = (const float*)d_in[5];
    const float* fc1w = (const float*)d_in[6];
    const float* fc1b = (const float*)d_in[7];
    const float* lng  = (const float*)d_in[8];
    const float* lnb  = (const float*)d_in[9];
    const float* fc2w = (const float*)d_in[10];
    const float* fc2b = (const float*)d_in[11];
    float* out = (float*)d_out;

    const int SM_MATCH = (2*SS*MPAD*2 + 2*SS + 4*SS + 2*SS) * 4;   // ~77.8KB
    const int SM_FGEMM = (SS*FPAD + 64*FPAD) * 4;                   // ~101.4KB
    const int SM_CONV  = (2*(CROWS+2)*(EE+2) + CROWS*EE + 18) * 4;  // ~62.8KB

    cudaFuncSetAttribute(k_match, cudaFuncAttributeMaxDynamicSharedMemorySize, SM_MATCH);
    cudaFuncSetAttribute(k_fgemm, cudaFuncAttributeMaxDynamicSharedMemorySize, SM_FGEMM);
    cudaFuncSetAttribute(k_conv,  cudaFuncAttributeMaxDynamicSharedMemorySize, SM_CONV);

    k_gather<<<BB, 256>>>(seq1, seq2, emb);
    k_mean0<<<dim3(BB, 3), 128>>>();
    for (int l = 0; l < LL; l++) {
        k_match<<<BB, 256, SM_MATCH>>>(0);
        k_zx<<<(BB*2*EE + 255)/256, 256>>>(l);
        k_fgemm<<<dim3(BB, 5), 256, SM_FGEMM>>>(W, l);
        k_conv<<<dim3(BB, 8, 2), 256, SM_CONV>>>(cw, cb, l);
        k_match<<<BB, 256, SM_MATCH>>>(1);
        k_pool<<<dim3(BB, 8, 2), 128>>>();
    }
    k_fc1<<<dim3(8, 5), 256>>>(fc1w);
    k_head<<<BB, 512>>>(fc1b, lng, lnb, fc2w, fc2b, out);
}